// round 11
// baseline (speedup 1.0000x reference)
#include <cuda_runtime.h>
#include <cuda_bf16.h>
#include <math.h>

// Problem constants
#define NNODES   4096      // 64 samples * 64 agents
#define NAG      64        // agents per sample
#define NSAMP    64
#define FDIM     128
#define ZW       258       // 2*F + 2
#define LN2F     0.69314718055994530942f

// ---------------- scratch (device globals; no allocations allowed) ----------
// Feature-major: g_E[g][f*NNODES + node].
// g: 0=A=exp(-Pf), 1=U=exp(-Qf), 2=B=exp(+Ps), 3=V=exp(+Qs)
__device__ __align__(16) float  g_E[4][FDIM * NNODES];
__device__ __align__(16) float  g_agg[NNODES * FDIM];    // [node][f]
__device__ __align__(16) float  g_x1[NNODES * FDIM];     // [node][f]
__device__ double g_sum[2][FDIM];
__device__ double g_sq[2][FDIM];
__device__ __align__(16) float g_sc[2][FDIM];
__device__ __align__(16) float g_sh[2][FDIM];
__device__ int    g_cnt[2];

// ---------------- mma helpers ------------------------------------------------
// fp32 fed to mma.tf32 without cvt — tensor core truncates to tf32 in HW
// (standard CUTLASS fp32 path; rel_err ~4e-4, under the 1e-3 gate).
__device__ __forceinline__ void mma_tf32(float c[4], const unsigned a[4], const unsigned b[2]) {
    asm volatile("mma.sync.aligned.m16n8k8.row.col.f32.tf32.tf32.f32 "
        "{%0,%1,%2,%3}, {%4,%5,%6,%7}, {%8,%9}, {%0,%1,%2,%3};"
        : "+f"(c[0]), "+f"(c[1]), "+f"(c[2]), "+f"(c[3])
        : "r"(a[0]), "r"(a[1]), "r"(a[2]), "r"(a[3]), "r"(b[0]), "r"(b[1]));
}
__device__ __forceinline__ void ldsm_x4(unsigned r[4], unsigned saddr) {
    asm volatile("ldmatrix.sync.aligned.m8n8.x4.shared.b16 {%0,%1,%2,%3}, [%4];"
        : "=r"(r[0]), "=r"(r[1]), "=r"(r[2]), "=r"(r[3]) : "r"(saddr));
}
__device__ __forceinline__ void ldsm_x2(unsigned r[2], unsigned saddr) {
    asm volatile("ldmatrix.sync.aligned.m8n8.x2.shared.b16 {%0,%1}, [%2];"
        : "=r"(r[0]), "=r"(r[1]) : "r"(saddr));
}
__device__ __forceinline__ unsigned smem_u32(const void* p) {
    unsigned a;
    asm("{ .reg .u64 t; cvta.to.shared.u64 t, %1; cvt.u32.u64 %0, t; }"
        : "=r"(a) : "l"(p));
    return a;
}
__device__ __forceinline__ void cp_async16(unsigned dst, const void* src) {
    asm volatile("cp.async.ca.shared.global [%0], [%1], 16;" :: "r"(dst), "l"(src));
}
__device__ __forceinline__ void cp_async_wait_all() {
    asm volatile("cp.async.commit_group;\n\tcp.async.wait_group 0;" ::: "memory");
}

// ---------------- f32x2 packed helpers (Blackwell) ---------------------------
__device__ __forceinline__ unsigned long long pack2(float lo, float hi) {
    unsigned long long r;
    asm("mov.b64 %0, {%1, %2};" : "=l"(r) : "f"(lo), "f"(hi));
    return r;
}
__device__ __forceinline__ void unpack2(unsigned long long p, float& lo, float& hi) {
    asm("mov.b64 {%0, %1}, %2;" : "=f"(lo), "=f"(hi) : "l"(p));
}
__device__ __forceinline__ unsigned long long fma2(unsigned long long a,
                                                   unsigned long long b,
                                                   unsigned long long c) {
    unsigned long long r;
    asm("fma.rn.f32x2 %0, %1, %2, %3;" : "=l"(r) : "l"(a), "l"(b), "l"(c));
    return r;
}
__device__ __forceinline__ unsigned long long mul2(unsigned long long a,
                                                   unsigned long long b) {
    unsigned long long r;
    asm("mul.rn.f32x2 %0, %1, %2;" : "=l"(r) : "l"(a), "l"(b));
    return r;
}

// ---------------- node GEMM (tf32 tensor core) + exp epilogue ---------------
// C[4096,512] = Xeff[4096,128] @ Wcat[512,128]^T, column n = g*128+f.
// Tile 64m x 64n, grid (64, 8) = 512 blocks, 256 threads (8 warps: 2m x 4n),
// warp tile 32m x 16n = 2x2 m16n8k8. K=128 smem-resident, 3 blocks/SM.
// fuse=1 (layer 2): Xeff = relu(BN1(agg) + x0) in prologue; blockIdx.y==0
// blocks also write Xeff to Xout.
#define XS_STRIDE 132
#define GEMM_SMEM_FLOATS (64*XS_STRIDE*2 + 64*3 + 64*2)
#define GEMM_SMEM_BYTES  (GEMM_SMEM_FLOATS * 4)

__global__ __launch_bounds__(256, 3) void k_gemm_tf32(
    const float* __restrict__ X,       // x0 (gnn_in) for both layers
    const float* __restrict__ AGG,     // layer-1 agg (fuse only)
    float* __restrict__ Xout,          // x1 destination (fuse only)
    const float* __restrict__ C2,
    const float* __restrict__ Wf, const float* __restrict__ bf,
    const float* __restrict__ Ws, const float* __restrict__ bs,
    int sidx, int fuse)
{
    extern __shared__ float smem[];
    float* Xs  = smem;                          // [64][132] fp32
    float* Wt  = Xs + 64 * XS_STRIDE;           // [64][132] fp32
    float* wA  = Wt + 64 * XS_STRIDE;           // [64]
    float* wB  = wA + 64;                       // [64]
    float* bb  = wB + 64;                       // [64]
    float* cs0 = bb + 64;                       // [64]
    float* cs1 = cs0 + 64;

    unsigned* Xu = (unsigned*)Xs;
    unsigned* Wu = (unsigned*)Wt;
    const unsigned XsA = smem_u32(Xs);

    const int tid = threadIdx.x;
    const int bm  = blockIdx.x * 64;
    const int bn  = blockIdx.y * 64;

    if (blockIdx.x == 0 && blockIdx.y == 0) {
        if (tid < FDIM) { g_sum[sidx][tid] = 0.0; g_sq[sidx][tid] = 0.0; }
        if (tid == 128) g_cnt[sidx] = 0;
    }

    // ---- X tile ----
    if (!fuse) {
        #pragma unroll
        for (int idx = tid; idx < 64 * 32; idx += 256) {
            int m = idx >> 5, kq = idx & 31;
            cp_async16(XsA + (m * XS_STRIDE + kq * 4) * 4,
                       X + (bm + m) * FDIM + kq * 4);
        }
        asm volatile("cp.async.commit_group;" ::: "memory");
    } else {
        #pragma unroll
        for (int idx = tid; idx < 64 * 32; idx += 256) {
            int m = idx >> 5, kq = idx & 31;
            float4 v  = ((const float4*)X)[(bm + m) * 32 + kq];
            float4 ag = ((const float4*)AGG)[(bm + m) * 32 + kq];
            float4 scv = *(const float4*)(g_sc[0] + kq * 4);
            float4 shv = *(const float4*)(g_sh[0] + kq * 4);
            v.x = fmaxf(fmaf(ag.x, scv.x, shv.x) + v.x, 0.f);
            v.y = fmaxf(fmaf(ag.y, scv.y, shv.y) + v.y, 0.f);
            v.z = fmaxf(fmaf(ag.z, scv.z, shv.z) + v.z, 0.f);
            v.w = fmaxf(fmaf(ag.w, scv.w, shv.w) + v.w, 0.f);
            if (blockIdx.y == 0) ((float4*)Xout)[(bm + m) * 32 + kq] = v;
            *(float4*)(Xs + m * XS_STRIDE + kq * 4) = v;
        }
    }

    // ---- W tile (plain LDG.64 + STS.64; W rows only 8B-aligned) ----
    #pragma unroll
    for (int idx = tid; idx < 64 * 64; idx += 256) {
        int cl = idx >> 6, kh = idx & 63;
        int n = bn + cl;
        int g = n >> 7, f = n & 127;
        const float* wb = ((g < 2) ? Wf : Ws) + f * ZW + ((g & 1) ? 128 : 0);
        float2 v = ((const float2*)wb)[kh];
        *(float2*)(Wt + cl * XS_STRIDE + kh * 2) = v;
    }

    // ---- small epilogue tables ----
    if (tid < 64) {
        int n = bn + tid;
        int g = n >> 7, f = n & 127;
        const float* wsel = (g < 2) ? Wf : Ws;
        float sgn = (g & 1) ? -1.f : 1.f;
        wA[tid] = sgn * wsel[f * ZW + 256];
        wB[tid] = sgn * wsel[f * ZW + 257];
        bb[tid] = (g == 0) ? bf[f] : ((g == 2) ? bs[f] : 0.f);
    }
    if (tid >= 64 && tid < 128) {
        int m = tid - 64;
        cs0[m] = C2[(bm + m) * 2 + 0];
        cs1[m] = C2[(bm + m) * 2 + 1];
    }
    if (!fuse) cp_async_wait_all();
    __syncthreads();

    const int wid   = tid >> 5;
    const int lane  = tid & 31;
    const int group = lane >> 2;
    const int tg    = lane & 3;
    const int wm    = (wid & 1) * 32;     // 2 warps along m
    const int wn    = (wid >> 1) * 16;    // 4 warps along n

    unsigned aAddr[2];
    {
        int q = lane >> 3, rq = lane & 7;
        int rowoff = (q & 1) * 8 + rq;
        int koff   = (q >> 1) * 4;
        #pragma unroll
        for (int mt = 0; mt < 2; mt++) {
            int r = wm + mt * 16 + rowoff;
            aAddr[mt] = smem_u32(&Xu[r * XS_STRIDE + koff]);
        }
    }
    unsigned bAddr[2];
    {
        int l16 = lane & 15;
        int rowoff = l16 & 7;
        int koff   = (l16 >> 3) * 4;
        #pragma unroll
        for (int nt = 0; nt < 2; nt++) {
            int nn = wn + nt * 8 + rowoff;
            bAddr[nt] = smem_u32(&Wu[nn * XS_STRIDE + koff]);
        }
    }

    float acc[2][2][4];
    #pragma unroll
    for (int mt = 0; mt < 2; mt++)
        #pragma unroll
        for (int nt = 0; nt < 2; nt++)
            #pragma unroll
            for (int c = 0; c < 4; c++) acc[mt][nt][c] = 0.f;

    unsigned af[2][2][4], bfr[2][2][2];
    #pragma unroll
    for (int mt = 0; mt < 2; mt++) ldsm_x4(af[0][mt], aAddr[mt]);
    #pragma unroll
    for (int nt = 0; nt < 2; nt++) ldsm_x2(bfr[0][nt], bAddr[nt]);

    #pragma unroll
    for (int ks = 0; ks < 16; ks++) {
        const int cur = ks & 1, nxt = cur ^ 1;
        if (ks < 15) {
            const unsigned koff = (unsigned)(ks + 1) * 32u;
            #pragma unroll
            for (int mt = 0; mt < 2; mt++) ldsm_x4(af[nxt][mt], aAddr[mt] + koff);
            #pragma unroll
            for (int nt = 0; nt < 2; nt++) ldsm_x2(bfr[nxt][nt], bAddr[nt] + koff);
        }
        #pragma unroll
        for (int mt = 0; mt < 2; mt++)
            #pragma unroll
            for (int nt = 0; nt < 2; nt++)
                mma_tf32(acc[mt][nt], af[cur][mt], bfr[cur][nt]);
    }

    // ---- epilogue: center term + bias + exp, feature-major scatter ----
    #pragma unroll
    for (int mt = 0; mt < 2; mt++) {
        int r0 = wm + mt * 16 + group;
        int r1 = r0 + 8;
        float a0 = cs0[r0], a1 = cs1[r0];
        float b0 = cs0[r1], b1 = cs1[r1];
        #pragma unroll
        for (int nt = 0; nt < 2; nt++) {
            int cl = wn + nt * 8 + 2 * tg;
            #pragma unroll
            for (int cc = 0; cc < 4; cc++) {
                int cll = cl + (cc & 1);
                int n = bn + cll;
                int g = n >> 7, f = n & 127;
                float mc0 = (cc < 2) ? a0 : b0;
                float mc1 = (cc < 2) ? a1 : b1;
                int rl = (cc < 2) ? r0 : r1;
                float t = acc[mt][nt][cc] + mc0 * wA[cll] + mc1 * wB[cll] + bb[cll];
                float v = __expf((g < 2) ? -t : t);
                g_E[g][f * NNODES + bm + rl] = v;
            }
        }
    }
}

// ---------------- edge aggregation (R7 version: 4 feat x 64 agents) ----------
// agg[i,f] = sum_{j != i} rcp(1 + A_i U_j) * ln2 * log2(1 + B_i V_j)
// 4-way rcp batching with f32x2 packed FMA math.
__global__ __launch_bounds__(256) void k_edge(int sidx,
    const float* __restrict__ gamma, const float* __restrict__ beta)
{
    __shared__ __align__(16) float su[4][64];
    __shared__ __align__(16) float sv[4][64];
    __shared__ float wsum[8], wsq[8];
    __shared__ int   lastflag;

    const int tid  = threadIdx.x;
    const int i    = tid & 63;
    const int fl   = tid >> 6;
    const int f    = blockIdx.y * 4 + fl;
    const int node = blockIdx.x * NAG + i;
    const int eidx = f * NNODES + node;

    const float a  = g_E[0][eidx];
    const float u  = g_E[1][eidx];
    const float b  = g_E[2][eidx];
    const float vv = g_E[3][eidx];
    su[fl][i] = u;
    sv[fl][i] = vv;
    __syncthreads();

    const ulonglong2* pu = (const ulonglong2*)su[fl];
    const ulonglong2* pv = (const ulonglong2*)sv[fl];

    const unsigned long long ONE2 = pack2(1.f, 1.f);
    const unsigned long long a2   = pack2(a, a);
    const unsigned long long b2   = pack2(b, b);

    float acc = 0.f;
    #pragma unroll
    for (int jq = 0; jq < 16; jq++) {
        ulonglong2 Uq = pu[jq];     // (u0,u1),(u2,u3)
        ulonglong2 Vq = pv[jq];
        unsigned long long t1a = fma2(a2, Uq.x, ONE2);   // (t0,t1)
        unsigned long long t1b = fma2(a2, Uq.y, ONE2);   // (t2,t3)
        unsigned long long t2a = fma2(b2, Vq.x, ONE2);
        unsigned long long t2b = fma2(b2, Vq.y, ONE2);
        float x0, x1, x2, x3;
        unpack2(t2a, x0, x1);
        unpack2(t2b, x2, x3);
        float l0 = __log2f(x0), l1 = __log2f(x1);
        float l2 = __log2f(x2), l3 = __log2f(x3);
        unsigned long long tt = mul2(t1a, t1b);          // (t0t2, t1t3)
        float ttl, tth;
        unpack2(tt, ttl, tth);
        float D = ttl * tth;
        float r;
        asm("rcp.approx.f32 %0, %1;" : "=f"(r) : "f"(D));
        unsigned long long lp01 = pack2(l0, l1);
        unsigned long long lp23 = pack2(l2, l3);
        unsigned long long m = fma2(lp23, t1a, mul2(lp01, t1b));  // (m0,m1)
        float m0, m1;
        unpack2(m, m0, m1);
        float s = fmaf(ttl, m1, tth * m0);
        acc = fmaf(s, r, acc);
    }
    // subtract self term (j == i)
    {
        float t1 = fmaf(a, u, 1.f);
        float t2 = fmaf(b, vv, 1.f);
        float r;
        asm("rcp.approx.f32 %0, %1;" : "=f"(r) : "f"(t1));
        acc -= r * __log2f(t2);
    }
    const float aggv = acc * LN2F;
    g_agg[node * FDIM + f] = aggv;

    // BN stats partial sums
    float s = aggv, q = aggv * aggv;
    #pragma unroll
    for (int o = 16; o > 0; o >>= 1) {
        s += __shfl_down_sync(0xFFFFFFFFu, s, o);
        q += __shfl_down_sync(0xFFFFFFFFu, q, o);
    }
    if ((tid & 31) == 0) { wsum[tid >> 5] = s; wsq[tid >> 5] = q; }
    __syncthreads();
    if (tid < 4) {
        double S = (double)wsum[2 * tid] + (double)wsum[2 * tid + 1];
        double Q = (double)wsq[2 * tid]  + (double)wsq[2 * tid + 1];
        int ff = blockIdx.y * 4 + tid;
        atomicAdd(&g_sum[sidx][ff], S);
        atomicAdd(&g_sq[sidx][ff], Q);
        __threadfence();
    }
    __syncthreads();

    if (tid == 0) {
        int prev = atomicAdd(&g_cnt[sidx], 1);
        lastflag = (prev == NSAMP * (FDIM / 4) - 1);
    }
    __syncthreads();
    if (lastflag) {
        if (tid < FDIM) {
            double S = __ldcg(&g_sum[sidx][tid]);
            double Q = __ldcg(&g_sq[sidx][tid]);
            double mean = S * (1.0 / NNODES);
            double var  = Q * (1.0 / NNODES) - mean * mean;
            float inv = (float)(1.0 / sqrt(var + 1e-5));
            float g = gamma[tid];
            g_sc[sidx][tid] = inv * g;
            g_sh[sidx][tid] = beta[tid] - (float)mean * inv * g;
        }
    }
}

// ---------------- BatchNorm + residual + ReLU (final output) ----------------
__global__ __launch_bounds__(256) void k_bn(
    const float* __restrict__ xin,
    float* __restrict__ out, int sidx)
{
    const int t = threadIdx.x;
    const float* sc = g_sc[sidx];
    const float* sh = g_sh[sidx];

    #pragma unroll
    for (int rep = 0; rep < 2; rep++) {
        int q4 = blockIdx.x * 512 + rep * 256 + t;
        int base = q4 * 4;
        int f = base & 127;
        float4 ag = *(const float4*)(g_agg + base);
        float4 xi = *(const float4*)(xin + base);
        float4 scv = *(const float4*)(sc + f);
        float4 shv = *(const float4*)(sh + f);
        float4 o;
        o.x = fmaxf(fmaf(ag.x, scv.x, shv.x) + xi.x, 0.f);
        o.y = fmaxf(fmaf(ag.y, scv.y, shv.y) + xi.y, 0.f);
        o.z = fmaxf(fmaf(ag.z, scv.z, shv.z) + xi.z, 0.f);
        o.w = fmaxf(fmaf(ag.w, scv.w, shv.w) + xi.w, 0.f);
        *(float4*)(out + base) = o;
    }
}

// ---------------- launcher ---------------------------------------------------
extern "C" void kernel_launch(void* const* d_in, const int* in_sizes, int n_in,
                              void* d_out, int out_size)
{
    const float* gnn_in  = (const float*)d_in[0];
    const float* centers = (const float*)d_in[1];
    const float* Wf1 = (const float*)d_in[4];
    const float* bf1 = (const float*)d_in[5];
    const float* Ws1 = (const float*)d_in[6];
    const float* bs1 = (const float*)d_in[7];
    const float* g1  = (const float*)d_in[8];
    const float* be1 = (const float*)d_in[9];
    const float* Wf2 = (const float*)d_in[10];
    const float* bf2 = (const float*)d_in[11];
    const float* Ws2 = (const float*)d_in[12];
    const float* bs2 = (const float*)d_in[13];
    const float* g2  = (const float*)d_in[14];
    const float* be2 = (const float*)d_in[15];
    float* out = (float*)d_out;

    float* x1;   cudaGetSymbolAddress((void**)&x1, g_x1);
    float* aggp; cudaGetSymbolAddress((void**)&aggp, g_agg);

    static int smem_set = 0;
    if (!smem_set) {
        cudaFuncSetAttribute(k_gemm_tf32,
                             cudaFuncAttributeMaxDynamicSharedMemorySize,
                             GEMM_SMEM_BYTES);
        smem_set = 1;
    }

    dim3 gemm_grid(NNODES / 64, 8);       // 64 x 8 = 512 blocks
    dim3 edge_grid(NSAMP, FDIM / 4);      // 64 x 32 blocks
    int bn_blocks = (NNODES * FDIM) / (4 * 512);

    // ---- layer 1 ----
    k_gemm_tf32<<<gemm_grid, 256, GEMM_SMEM_BYTES>>>(
        gnn_in, gnn_in, x1, centers, Wf1, bf1, Ws1, bs1, 0, 0);
    k_edge<<<edge_grid, 256>>>(0, g1, be1);

    // ---- layer 2 (BN1 + residual + ReLU fused into the GEMM prologue) ----
    k_gemm_tf32<<<gemm_grid, 256, GEMM_SMEM_BYTES>>>(
        gnn_in, aggp, x1, centers, Wf2, bf2, Ws2, bs2, 1, 1);
    k_edge<<<edge_grid, 256>>>(1, g2, be2);
    k_bn<<<bn_blocks, 256>>>(x1, out, 1);
}

// round 12
// speedup vs baseline: 1.0718x; 1.0718x over previous
#include <cuda_runtime.h>
#include <cuda_bf16.h>
#include <math.h>

// Problem constants
#define NNODES   4096      // 64 samples * 64 agents
#define NAG      64        // agents per sample
#define NSAMP    64
#define FDIM     128
#define ZW       258       // 2*F + 2
#define LN2F     0.69314718055994530942f

// ---------------- scratch (device globals; no allocations allowed) ----------
// Feature-major: g_E[g][f*NNODES + node].
// g: 0=A=exp(-Pf), 1=U=exp(-Qf), 2=B=exp(+Ps), 3=V=exp(+Qs)
__device__ __align__(16) float  g_E[4][FDIM * NNODES];
__device__ __align__(16) float  g_agg[NNODES * FDIM];    // [node][f]
__device__ __align__(16) float  g_x1[NNODES * FDIM];     // [node][f]
__device__ double g_sum[2][FDIM];
__device__ double g_sq[2][FDIM];
__device__ __align__(16) float g_sc[2][FDIM];
__device__ __align__(16) float g_sh[2][FDIM];
__device__ int    g_cnt[2];

// ---------------- mma helpers ------------------------------------------------
// fp32 fed to mma.tf32 without cvt — tensor core truncates to tf32 in HW
// (standard CUTLASS fp32 path; measured rel_err ~4e-4, under the 1e-3 gate).
__device__ __forceinline__ void mma_tf32(float c[4], const unsigned a[4], const unsigned b[2]) {
    asm volatile("mma.sync.aligned.m16n8k8.row.col.f32.tf32.tf32.f32 "
        "{%0,%1,%2,%3}, {%4,%5,%6,%7}, {%8,%9}, {%0,%1,%2,%3};"
        : "+f"(c[0]), "+f"(c[1]), "+f"(c[2]), "+f"(c[3])
        : "r"(a[0]), "r"(a[1]), "r"(a[2]), "r"(a[3]), "r"(b[0]), "r"(b[1]));
}
__device__ __forceinline__ void ldsm_x4(unsigned r[4], unsigned saddr) {
    asm volatile("ldmatrix.sync.aligned.m8n8.x4.shared.b16 {%0,%1,%2,%3}, [%4];"
        : "=r"(r[0]), "=r"(r[1]), "=r"(r[2]), "=r"(r[3]) : "r"(saddr));
}
__device__ __forceinline__ void ldsm_x2(unsigned r[2], unsigned saddr) {
    asm volatile("ldmatrix.sync.aligned.m8n8.x2.shared.b16 {%0,%1}, [%2];"
        : "=r"(r[0]), "=r"(r[1]) : "r"(saddr));
}
__device__ __forceinline__ unsigned smem_u32(const void* p) {
    unsigned a;
    asm("{ .reg .u64 t; cvta.to.shared.u64 t, %1; cvt.u32.u64 %0, t; }"
        : "=r"(a) : "l"(p));
    return a;
}

// ---------------- f32x2 packed helpers (Blackwell) ---------------------------
__device__ __forceinline__ unsigned long long pack2(float lo, float hi) {
    unsigned long long r;
    asm("mov.b64 %0, {%1, %2};" : "=l"(r) : "f"(lo), "f"(hi));
    return r;
}
__device__ __forceinline__ void unpack2(unsigned long long p, float& lo, float& hi) {
    asm("mov.b64 {%0, %1}, %2;" : "=f"(lo), "=f"(hi) : "l"(p));
}
__device__ __forceinline__ unsigned long long fma2(unsigned long long a,
                                                   unsigned long long b,
                                                   unsigned long long c) {
    unsigned long long r;
    asm("fma.rn.f32x2 %0, %1, %2, %3;" : "=l"(r) : "l"(a), "l"(b), "l"(c));
    return r;
}
__device__ __forceinline__ unsigned long long mul2(unsigned long long a,
                                                   unsigned long long b) {
    unsigned long long r;
    asm("mul.rn.f32x2 %0, %1, %2;" : "=l"(r) : "l"(a), "l"(b));
    return r;
}

// ---------------- node GEMM (tf32 tensor core) + exp epilogue ---------------
// C[4096,512] = Xeff[4096,128] @ Wcat[512,128]^T, column n = g*128+f.
// Block tile 128m x 64n, grid (32, 8) = 256 blocks, 256 threads
// (8 warps: 4m x 2n), warp tile 32m x 32n = 2x4 m16n8k8, K=128 smem-resident.
// Fragments via ldmatrix, 2-deep register pipeline. Plain LDG/STS prologue
// (R7-proven); NO cvt — fp32 bits fed to mma.tf32 directly.
// fuse=1 (layer 2): Xeff = relu(BN1(agg) + x0) in prologue; blockIdx.y==0
// blocks also write Xeff to Xout.
#define XS_STRIDE 132
#define GEMM_SMEM_FLOATS (128*XS_STRIDE + 64*XS_STRIDE + 64*3 + 128*2)
#define GEMM_SMEM_BYTES  (GEMM_SMEM_FLOATS * 4)

__global__ __launch_bounds__(256, 2) void k_gemm_tf32(
    const float* __restrict__ X,       // x0 (gnn_in) for both layers
    const float* __restrict__ AGG,     // layer-1 agg (fuse only)
    float* __restrict__ Xout,          // x1 destination (fuse only)
    const float* __restrict__ C2,
    const float* __restrict__ Wf, const float* __restrict__ bf,
    const float* __restrict__ Ws, const float* __restrict__ bs,
    int sidx, int fuse)
{
    extern __shared__ float smem[];
    float* Xs  = smem;                          // [128][132] fp32
    float* Wt  = Xs + 128 * XS_STRIDE;          // [64][132]  fp32
    float* wA  = Wt + 64 * XS_STRIDE;           // [64]
    float* wB  = wA + 64;                       // [64]
    float* bb  = wB + 64;                       // [64]
    float* cs0 = bb + 64;                       // [128]
    float* cs1 = cs0 + 128;

    unsigned* Xu = (unsigned*)Xs;
    unsigned* Wu = (unsigned*)Wt;

    const int tid = threadIdx.x;
    const int bm  = blockIdx.x * 128;
    const int bn  = blockIdx.y * 64;

    if (blockIdx.x == 0 && blockIdx.y == 0) {
        if (tid < FDIM) { g_sum[sidx][tid] = 0.0; g_sq[sidx][tid] = 0.0; }
        if (tid == 128) g_cnt[sidx] = 0;
    }

    // ---- X tile (raw fp32 into smem) ----
    if (!fuse) {
        #pragma unroll
        for (int idx = tid; idx < 128 * 32; idx += 256) {
            int m = idx >> 5, kq = idx & 31;
            float4 v = ((const float4*)X)[(bm + m) * 32 + kq];
            *(float4*)(Xs + m * XS_STRIDE + kq * 4) = v;
        }
    } else {
        #pragma unroll
        for (int idx = tid; idx < 128 * 32; idx += 256) {
            int m = idx >> 5, kq = idx & 31;
            float4 v  = ((const float4*)X)[(bm + m) * 32 + kq];
            float4 ag = ((const float4*)AGG)[(bm + m) * 32 + kq];
            float4 scv = *(const float4*)(g_sc[0] + kq * 4);
            float4 shv = *(const float4*)(g_sh[0] + kq * 4);
            v.x = fmaxf(fmaf(ag.x, scv.x, shv.x) + v.x, 0.f);
            v.y = fmaxf(fmaf(ag.y, scv.y, shv.y) + v.y, 0.f);
            v.z = fmaxf(fmaf(ag.z, scv.z, shv.z) + v.z, 0.f);
            v.w = fmaxf(fmaf(ag.w, scv.w, shv.w) + v.w, 0.f);
            if (blockIdx.y == 0) ((float4*)Xout)[(bm + m) * 32 + kq] = v;
            *(float4*)(Xs + m * XS_STRIDE + kq * 4) = v;
        }
    }
    // ---- W tile (LDG.64 + STS.64; W rows only 8B-aligned) ----
    #pragma unroll
    for (int idx = tid; idx < 64 * 64; idx += 256) {
        int cl = idx >> 6, kh = idx & 63;
        int n = bn + cl;
        int g = n >> 7, f = n & 127;
        const float* wb = ((g < 2) ? Wf : Ws) + f * ZW + ((g & 1) ? 128 : 0);
        float2 v = ((const float2*)wb)[kh];
        *(float2*)(Wt + cl * XS_STRIDE + kh * 2) = v;
    }
    // ---- small epilogue tables ----
    if (tid < 64) {
        int n = bn + tid;
        int g = n >> 7, f = n & 127;
        const float* wsel = (g < 2) ? Wf : Ws;
        float sgn = (g & 1) ? -1.f : 1.f;
        wA[tid] = sgn * wsel[f * ZW + 256];
        wB[tid] = sgn * wsel[f * ZW + 257];
        bb[tid] = (g == 0) ? bf[f] : ((g == 2) ? bs[f] : 0.f);
    }
    if (tid < 128) {
        cs0[tid] = C2[(bm + tid) * 2 + 0];
        cs1[tid] = C2[(bm + tid) * 2 + 1];
    }
    __syncthreads();

    const int wid   = tid >> 5;
    const int lane  = tid & 31;
    const int group = lane >> 2;
    const int tg    = lane & 3;
    const int wm    = (wid & 3) * 32;
    const int wn    = (wid >> 2) * 32;

    unsigned aAddr[2];
    {
        int q = lane >> 3, rq = lane & 7;
        int rowoff = (q & 1) * 8 + rq;
        int koff   = (q >> 1) * 4;
        #pragma unroll
        for (int mt = 0; mt < 2; mt++) {
            int r = wm + mt * 16 + rowoff;
            aAddr[mt] = smem_u32(&Xu[r * XS_STRIDE + koff]);
        }
    }
    unsigned bAddr[4];
    {
        int l16 = lane & 15;
        int rowoff = l16 & 7;
        int koff   = (l16 >> 3) * 4;
        #pragma unroll
        for (int nt = 0; nt < 4; nt++) {
            int nn = wn + nt * 8 + rowoff;
            bAddr[nt] = smem_u32(&Wu[nn * XS_STRIDE + koff]);
        }
    }

    float acc[2][4][4];
    #pragma unroll
    for (int mt = 0; mt < 2; mt++)
        #pragma unroll
        for (int nt = 0; nt < 4; nt++)
            #pragma unroll
            for (int c = 0; c < 4; c++) acc[mt][nt][c] = 0.f;

    unsigned af[2][2][4], bfr[2][4][2];
    #pragma unroll
    for (int mt = 0; mt < 2; mt++) ldsm_x4(af[0][mt], aAddr[mt]);
    #pragma unroll
    for (int nt = 0; nt < 4; nt++) ldsm_x2(bfr[0][nt], bAddr[nt]);

    #pragma unroll
    for (int ks = 0; ks < 16; ks++) {
        const int cur = ks & 1, nxt = cur ^ 1;
        if (ks < 15) {
            const unsigned koff = (unsigned)(ks + 1) * 32u;
            #pragma unroll
            for (int mt = 0; mt < 2; mt++) ldsm_x4(af[nxt][mt], aAddr[mt] + koff);
            #pragma unroll
            for (int nt = 0; nt < 4; nt++) ldsm_x2(bfr[nxt][nt], bAddr[nt] + koff);
        }
        #pragma unroll
        for (int mt = 0; mt < 2; mt++)
            #pragma unroll
            for (int nt = 0; nt < 4; nt++)
                mma_tf32(acc[mt][nt], af[cur][mt], bfr[cur][nt]);
    }

    // ---- epilogue: center term + bias + exp, feature-major scatter ----
    #pragma unroll
    for (int mt = 0; mt < 2; mt++) {
        int r0 = wm + mt * 16 + group;
        int r1 = r0 + 8;
        float a0 = cs0[r0], a1 = cs1[r0];
        float b0 = cs0[r1], b1 = cs1[r1];
        #pragma unroll
        for (int nt = 0; nt < 4; nt++) {
            int cl = wn + nt * 8 + 2 * tg;
            #pragma unroll
            for (int cc = 0; cc < 4; cc++) {
                int cll = cl + (cc & 1);
                int n = bn + cll;
                int g = n >> 7, f = n & 127;
                float mc0 = (cc < 2) ? a0 : b0;
                float mc1 = (cc < 2) ? a1 : b1;
                int rl = (cc < 2) ? r0 : r1;
                float t = acc[mt][nt][cc] + mc0 * wA[cll] + mc1 * wB[cll] + bb[cll];
                float v = __expf((g < 2) ? -t : t);
                g_E[g][f * NNODES + bm + rl] = v;
            }
        }
    }
}

// ---------------- edge aggregation (R7 version: 4 feat x 64 agents) ----------
// agg[i,f] = sum_{j != i} rcp(1 + A_i U_j) * ln2 * log2(1 + B_i V_j)
// 4-way rcp batching with f32x2 packed FMA math.
__global__ __launch_bounds__(256) void k_edge(int sidx,
    const float* __restrict__ gamma, const float* __restrict__ beta)
{
    __shared__ __align__(16) float su[4][64];
    __shared__ __align__(16) float sv[4][64];
    __shared__ float wsum[8], wsq[8];
    __shared__ int   lastflag;

    const int tid  = threadIdx.x;
    const int i    = tid & 63;
    const int fl   = tid >> 6;
    const int f    = blockIdx.y * 4 + fl;
    const int node = blockIdx.x * NAG + i;
    const int eidx = f * NNODES + node;

    const float a  = g_E[0][eidx];
    const float u  = g_E[1][eidx];
    const float b  = g_E[2][eidx];
    const float vv = g_E[3][eidx];
    su[fl][i] = u;
    sv[fl][i] = vv;
    __syncthreads();

    const ulonglong2* pu = (const ulonglong2*)su[fl];
    const ulonglong2* pv = (const ulonglong2*)sv[fl];

    const unsigned long long ONE2 = pack2(1.f, 1.f);
    const unsigned long long a2   = pack2(a, a);
    const unsigned long long b2   = pack2(b, b);

    float acc = 0.f;
    #pragma unroll
    for (int jq = 0; jq < 16; jq++) {
        ulonglong2 Uq = pu[jq];     // (u0,u1),(u2,u3)
        ulonglong2 Vq = pv[jq];
        unsigned long long t1a = fma2(a2, Uq.x, ONE2);   // (t0,t1)
        unsigned long long t1b = fma2(a2, Uq.y, ONE2);   // (t2,t3)
        unsigned long long t2a = fma2(b2, Vq.x, ONE2);
        unsigned long long t2b = fma2(b2, Vq.y, ONE2);
        float x0, x1, x2, x3;
        unpack2(t2a, x0, x1);
        unpack2(t2b, x2, x3);
        float l0 = __log2f(x0), l1 = __log2f(x1);
        float l2 = __log2f(x2), l3 = __log2f(x3);
        unsigned long long tt = mul2(t1a, t1b);          // (t0t2, t1t3)
        float ttl, tth;
        unpack2(tt, ttl, tth);
        float D = ttl * tth;
        float r;
        asm("rcp.approx.f32 %0, %1;" : "=f"(r) : "f"(D));
        unsigned long long lp01 = pack2(l0, l1);
        unsigned long long lp23 = pack2(l2, l3);
        unsigned long long m = fma2(lp23, t1a, mul2(lp01, t1b));  // (m0,m1)
        float m0, m1;
        unpack2(m, m0, m1);
        float s = fmaf(ttl, m1, tth * m0);
        acc = fmaf(s, r, acc);
    }
    // subtract self term (j == i)
    {
        float t1 = fmaf(a, u, 1.f);
        float t2 = fmaf(b, vv, 1.f);
        float r;
        asm("rcp.approx.f32 %0, %1;" : "=f"(r) : "f"(t1));
        acc -= r * __log2f(t2);
    }
    const float aggv = acc * LN2F;
    g_agg[node * FDIM + f] = aggv;

    // BN stats partial sums
    float s = aggv, q = aggv * aggv;
    #pragma unroll
    for (int o = 16; o > 0; o >>= 1) {
        s += __shfl_down_sync(0xFFFFFFFFu, s, o);
        q += __shfl_down_sync(0xFFFFFFFFu, q, o);
    }
    if ((tid & 31) == 0) { wsum[tid >> 5] = s; wsq[tid >> 5] = q; }
    __syncthreads();
    if (tid < 4) {
        double S = (double)wsum[2 * tid] + (double)wsum[2 * tid + 1];
        double Q = (double)wsq[2 * tid]  + (double)wsq[2 * tid + 1];
        int ff = blockIdx.y * 4 + tid;
        atomicAdd(&g_sum[sidx][ff], S);
        atomicAdd(&g_sq[sidx][ff], Q);
        __threadfence();
    }
    __syncthreads();

    if (tid == 0) {
        int prev = atomicAdd(&g_cnt[sidx], 1);
        lastflag = (prev == NSAMP * (FDIM / 4) - 1);
    }
    __syncthreads();
    if (lastflag) {
        if (tid < FDIM) {
            double S = __ldcg(&g_sum[sidx][tid]);
            double Q = __ldcg(&g_sq[sidx][tid]);
            double mean = S * (1.0 / NNODES);
            double var  = Q * (1.0 / NNODES) - mean * mean;
            float inv = (float)(1.0 / sqrt(var + 1e-5));
            float g = gamma[tid];
            g_sc[sidx][tid] = inv * g;
            g_sh[sidx][tid] = beta[tid] - (float)mean * inv * g;
        }
    }
}

// ---------------- BatchNorm + residual + ReLU (final output) ----------------
__global__ __launch_bounds__(256) void k_bn(
    const float* __restrict__ xin,
    float* __restrict__ out, int sidx)
{
    const int t = threadIdx.x;
    const float* sc = g_sc[sidx];
    const float* sh = g_sh[sidx];

    #pragma unroll
    for (int rep = 0; rep < 2; rep++) {
        int q4 = blockIdx.x * 512 + rep * 256 + t;
        int base = q4 * 4;
        int f = base & 127;
        float4 ag = *(const float4*)(g_agg + base);
        float4 xi = *(const float4*)(xin + base);
        float4 scv = *(const float4*)(sc + f);
        float4 shv = *(const float4*)(sh + f);
        float4 o;
        o.x = fmaxf(fmaf(ag.x, scv.x, shv.x) + xi.x, 0.f);
        o.y = fmaxf(fmaf(ag.y, scv.y, shv.y) + xi.y, 0.f);
        o.z = fmaxf(fmaf(ag.z, scv.z, shv.z) + xi.z, 0.f);
        o.w = fmaxf(fmaf(ag.w, scv.w, shv.w) + xi.w, 0.f);
        *(float4*)(out + base) = o;
    }
}

// ---------------- launcher ---------------------------------------------------
extern "C" void kernel_launch(void* const* d_in, const int* in_sizes, int n_in,
                              void* d_out, int out_size)
{
    const float* gnn_in  = (const float*)d_in[0];
    const float* centers = (const float*)d_in[1];
    const float* Wf1 = (const float*)d_in[4];
    const float* bf1 = (const float*)d_in[5];
    const float* Ws1 = (const float*)d_in[6];
    const float* bs1 = (const float*)d_in[7];
    const float* g1  = (const float*)d_in[8];
    const float* be1 = (const float*)d_in[9];
    const float* Wf2 = (const float*)d_in[10];
    const float* bf2 = (const float*)d_in[11];
    const float* Ws2 = (const float*)d_in[12];
    const float* bs2 = (const float*)d_in[13];
    const float* g2  = (const float*)d_in[14];
    const float* be2 = (const float*)d_in[15];
    float* out = (float*)d_out;

    float* x1;   cudaGetSymbolAddress((void**)&x1, g_x1);
    float* aggp; cudaGetSymbolAddress((void**)&aggp, g_agg);

    static int smem_set = 0;
    if (!smem_set) {
        cudaFuncSetAttribute(k_gemm_tf32,
                             cudaFuncAttributeMaxDynamicSharedMemorySize,
                             GEMM_SMEM_BYTES);
        smem_set = 1;
    }

    dim3 gemm_grid(NNODES / 128, 8);      // 32 x 8 = 256 blocks
    dim3 edge_grid(NSAMP, FDIM / 4);      // 64 x 32 blocks
    int bn_blocks = (NNODES * FDIM) / (4 * 512);

    // ---- layer 1 ----
    k_gemm_tf32<<<gemm_grid, 256, GEMM_SMEM_BYTES>>>(
        gnn_in, gnn_in, x1, centers, Wf1, bf1, Ws1, bs1, 0, 0);
    k_edge<<<edge_grid, 256>>>(0, g1, be1);

    // ---- layer 2 (BN1 + residual + ReLU fused into the GEMM prologue) ----
    k_gemm_tf32<<<gemm_grid, 256, GEMM_SMEM_BYTES>>>(
        gnn_in, aggp, x1, centers, Wf2, bf2, Ws2, bs2, 1, 1);
    k_edge<<<edge_grid, 256>>>(1, g2, be2);
    k_bn<<<bn_blocks, 256>>>(x1, out, 1);
}

// round 13
// speedup vs baseline: 1.1741x; 1.0954x over previous
#include <cuda_runtime.h>
#include <cuda_bf16.h>
#include <math.h>

// Problem constants
#define NNODES   4096      // 64 samples * 64 agents
#define NAG      64        // agents per sample
#define NSAMP    64
#define FDIM     128
#define ZW       258       // 2*F + 2
#define LN2F     0.69314718055994530942f

// ---------------- scratch (device globals; no allocations allowed) ----------
// Feature-major: g_E[g][f*NNODES + node].
// g: 0=A=exp(-Pf), 1=U=exp(-Qf), 2=B=exp(+Ps), 3=V=exp(+Qs)
__device__ __align__(16) float  g_E[4][FDIM * NNODES];
__device__ __align__(16) float  g_agg[NNODES * FDIM];    // [node][f]
__device__ __align__(16) float  g_x1[NNODES * FDIM];     // [node][f]
__device__ double g_sum[2][FDIM];
__device__ double g_sq[2][FDIM];
__device__ __align__(16) float g_sc[2][FDIM];
__device__ __align__(16) float g_sh[2][FDIM];
__device__ int    g_cnt[2];

// ---------------- mma helpers ------------------------------------------------
// fp32 fed to mma.tf32 without cvt — tensor core truncates to tf32 in HW.
__device__ __forceinline__ void mma_tf32(float c[4], const unsigned a[4], const unsigned b[2]) {
    asm volatile("mma.sync.aligned.m16n8k8.row.col.f32.tf32.tf32.f32 "
        "{%0,%1,%2,%3}, {%4,%5,%6,%7}, {%8,%9}, {%0,%1,%2,%3};"
        : "+f"(c[0]), "+f"(c[1]), "+f"(c[2]), "+f"(c[3])
        : "r"(a[0]), "r"(a[1]), "r"(a[2]), "r"(a[3]), "r"(b[0]), "r"(b[1]));
}
__device__ __forceinline__ void ldsm_x4(unsigned r[4], unsigned saddr) {
    asm volatile("ldmatrix.sync.aligned.m8n8.x4.shared.b16 {%0,%1,%2,%3}, [%4];"
        : "=r"(r[0]), "=r"(r[1]), "=r"(r[2]), "=r"(r[3]) : "r"(saddr));
}
__device__ __forceinline__ unsigned smem_u32(const void* p) {
    unsigned a;
    asm("{ .reg .u64 t; cvta.to.shared.u64 t, %1; cvt.u32.u64 %0, t; }"
        : "=r"(a) : "l"(p));
    return a;
}

// ---------------- f32x2 packed helpers (Blackwell) ---------------------------
__device__ __forceinline__ unsigned long long pack2(float lo, float hi) {
    unsigned long long r;
    asm("mov.b64 %0, {%1, %2};" : "=l"(r) : "f"(lo), "f"(hi));
    return r;
}
__device__ __forceinline__ void unpack2(unsigned long long p, float& lo, float& hi) {
    asm("mov.b64 {%0, %1}, %2;" : "=f"(lo), "=f"(hi) : "l"(p));
}
__device__ __forceinline__ unsigned long long fma2(unsigned long long a,
                                                   unsigned long long b,
                                                   unsigned long long c) {
    unsigned long long r;
    asm("fma.rn.f32x2 %0, %1, %2, %3;" : "=l"(r) : "l"(a), "l"(b), "l"(c));
    return r;
}
__device__ __forceinline__ unsigned long long mul2(unsigned long long a,
                                                   unsigned long long b) {
    unsigned long long r;
    asm("mul.rn.f32x2 %0, %1, %2;" : "=l"(r) : "l"(a), "l"(b));
    return r;
}

// ---------------- node GEMM (tf32 tensor core) + exp epilogue ---------------
// C[4096,512] = Xeff[4096,128] @ Wcat[512,128]^T.
// Tile 128m x 128n, grid (32, 4): blockIdx.y == g exactly (one exp-group per
// block, uniform sign/bias/W-base). 1 block/SM, single wave of 128 blocks.
// 8 warps: 4 along m (warp 32m) x 2 along n (warp 64n); warp tile = 2x8
// m16n8k8 tiles, acc 64 regs. K=128 smem-resident; ldmatrix x4 for A and B
// (B x4 = two stacked n-tiles), 2-deep register pipeline over k-steps.
// fuse=1 (layer 2): Xeff = relu(BN1(agg) + x0) in prologue; blockIdx.y==0
// blocks also write Xeff to Xout.
#define XS_STRIDE 132
#define GEMM_SMEM_FLOATS (128*XS_STRIDE*2 + 128*3 + 128*2)
#define GEMM_SMEM_BYTES  (GEMM_SMEM_FLOATS * 4)

__global__ __launch_bounds__(256, 1) void k_gemm_tf32(
    const float* __restrict__ X,       // x0 (gnn_in) for both layers
    const float* __restrict__ AGG,     // layer-1 agg (fuse only)
    float* __restrict__ Xout,          // x1 destination (fuse only)
    const float* __restrict__ C2,
    const float* __restrict__ Wf, const float* __restrict__ bf,
    const float* __restrict__ Ws, const float* __restrict__ bs,
    int sidx, int fuse)
{
    extern __shared__ float smem[];
    float* Xs  = smem;                          // [128][132] fp32
    float* Wt  = Xs + 128 * XS_STRIDE;          // [128][132] fp32
    float* wA  = Wt + 128 * XS_STRIDE;          // [128]
    float* wB  = wA + 128;                      // [128]
    float* bb  = wB + 128;                      // [128]
    float* cs0 = bb + 128;                      // [128]
    float* cs1 = cs0 + 128;

    unsigned* Xu = (unsigned*)Xs;
    unsigned* Wu = (unsigned*)Wt;

    const int tid = threadIdx.x;
    const int bm  = blockIdx.x * 128;
    const int g   = blockIdx.y;                 // exp group 0..3
    const int qoff = (g & 1) ? 128 : 0;
    const float* wsel = (g < 2) ? Wf : Ws;

    if (blockIdx.x == 0 && g == 0) {
        if (tid < FDIM) { g_sum[sidx][tid] = 0.0; g_sq[sidx][tid] = 0.0; }
        if (tid == 128) g_cnt[sidx] = 0;
    }

    // ---- X tile (raw fp32 into smem) ----
    if (!fuse) {
        #pragma unroll
        for (int idx = tid; idx < 128 * 32; idx += 256) {
            int m = idx >> 5, kq = idx & 31;
            float4 v = ((const float4*)X)[(bm + m) * 32 + kq];
            *(float4*)(Xs + m * XS_STRIDE + kq * 4) = v;
        }
    } else {
        #pragma unroll
        for (int idx = tid; idx < 128 * 32; idx += 256) {
            int m = idx >> 5, kq = idx & 31;
            float4 v  = ((const float4*)X)[(bm + m) * 32 + kq];
            float4 ag = ((const float4*)AGG)[(bm + m) * 32 + kq];
            float4 scv = *(const float4*)(g_sc[0] + kq * 4);
            float4 shv = *(const float4*)(g_sh[0] + kq * 4);
            v.x = fmaxf(fmaf(ag.x, scv.x, shv.x) + v.x, 0.f);
            v.y = fmaxf(fmaf(ag.y, scv.y, shv.y) + v.y, 0.f);
            v.z = fmaxf(fmaf(ag.z, scv.z, shv.z) + v.z, 0.f);
            v.w = fmaxf(fmaf(ag.w, scv.w, shv.w) + v.w, 0.f);
            if (g == 0) ((float4*)Xout)[(bm + m) * 32 + kq] = v;
            *(float4*)(Xs + m * XS_STRIDE + kq * 4) = v;
        }
    }
    // ---- W tile: 128 rows (= features of this g) x 128 K ----
    #pragma unroll
    for (int idx = tid; idx < 128 * 64; idx += 256) {
        int f = idx >> 6, kh = idx & 63;
        const float* wb = wsel + f * ZW + qoff;
        float2 v = ((const float2*)wb)[kh];
        *(float2*)(Wt + f * XS_STRIDE + kh * 2) = v;
    }
    // ---- epilogue tables (uniform g) ----
    if (tid < 128) {
        int f = tid;
        float sgn = (g & 1) ? -1.f : 1.f;
        wA[f] = sgn * wsel[f * ZW + 256];
        wB[f] = sgn * wsel[f * ZW + 257];
        bb[f] = (g == 0) ? bf[f] : ((g == 2) ? bs[f] : 0.f);
    } else {
        int m = tid - 128;
        cs0[m] = C2[(bm + m) * 2 + 0];
        cs1[m] = C2[(bm + m) * 2 + 1];
    }
    __syncthreads();

    const int wid   = tid >> 5;
    const int lane  = tid & 31;
    const int group = lane >> 2;
    const int tg    = lane & 3;
    const int wm    = (wid & 3) * 32;     // 4 warps along m
    const int wn    = (wid >> 2) * 64;    // 2 warps along n

    // A ldmatrix.x4 lane mapping: q0:(r,k0) q1:(r+8,k0) q2:(r,k4) q3:(r+8,k4)
    unsigned aAddr[2];
    {
        int q = lane >> 3, rq = lane & 7;
        int rowoff = (q & 1) * 8 + rq;
        int koff   = (q >> 1) * 4;
        #pragma unroll
        for (int mt = 0; mt < 2; mt++) {
            int r = wm + mt * 16 + rowoff;
            aAddr[mt] = smem_u32(&Xu[r * XS_STRIDE + koff]);
        }
    }
    // B ldmatrix.x4 (two stacked n-tiles): q0:(n,k0) q1:(n,k4) q2:(n+8,k0) q3:(n+8,k4)
    unsigned bAddr[4];
    {
        int q = lane >> 3, rq = lane & 7;
        int rowoff = (q >> 1) * 8 + rq;
        int koff   = (q & 1) * 4;
        #pragma unroll
        for (int p = 0; p < 4; p++) {           // pair p covers n-tiles 2p, 2p+1
            int nn = wn + p * 16 + rowoff;
            bAddr[p] = smem_u32(&Wu[nn * XS_STRIDE + koff]);
        }
    }

    float acc[2][8][4];
    #pragma unroll
    for (int mt = 0; mt < 2; mt++)
        #pragma unroll
        for (int nt = 0; nt < 8; nt++)
            #pragma unroll
            for (int c = 0; c < 4; c++) acc[mt][nt][c] = 0.f;

    unsigned af[2][2][4], bfr[2][4][4];
    #pragma unroll
    for (int mt = 0; mt < 2; mt++) ldsm_x4(af[0][mt], aAddr[mt]);
    #pragma unroll
    for (int p = 0; p < 4; p++) ldsm_x4(bfr[0][p], bAddr[p]);

    #pragma unroll
    for (int ks = 0; ks < 16; ks++) {
        const int cur = ks & 1, nxt = cur ^ 1;
        if (ks < 15) {
            const unsigned koff = (unsigned)(ks + 1) * 32u;
            #pragma unroll
            for (int mt = 0; mt < 2; mt++) ldsm_x4(af[nxt][mt], aAddr[mt] + koff);
            #pragma unroll
            for (int p = 0; p < 4; p++) ldsm_x4(bfr[nxt][p], bAddr[p] + koff);
        }
        #pragma unroll
        for (int mt = 0; mt < 2; mt++)
            #pragma unroll
            for (int p = 0; p < 4; p++) {
                mma_tf32(acc[mt][2 * p + 0], af[cur][mt], &bfr[cur][p][0]);
                mma_tf32(acc[mt][2 * p + 1], af[cur][mt], &bfr[cur][p][2]);
            }
    }

    // ---- epilogue: center term + bias + exp, feature-major scatter ----
    float* Eg = g_E[g];
    #pragma unroll
    for (int mt = 0; mt < 2; mt++) {
        int r0 = wm + mt * 16 + group;
        int r1 = r0 + 8;
        float a0 = cs0[r0], a1 = cs1[r0];
        float b0 = cs0[r1], b1 = cs1[r1];
        #pragma unroll
        for (int nt = 0; nt < 8; nt++) {
            int cl = wn + nt * 8 + 2 * tg;
            #pragma unroll
            for (int cc = 0; cc < 4; cc++) {
                int f = cl + (cc & 1);
                float mc0 = (cc < 2) ? a0 : b0;
                float mc1 = (cc < 2) ? a1 : b1;
                int rl = (cc < 2) ? r0 : r1;
                float t = acc[mt][nt][cc] + mc0 * wA[f] + mc1 * wB[f] + bb[f];
                float v = __expf((g < 2) ? -t : t);
                Eg[f * NNODES + bm + rl] = v;
            }
        }
    }
}

// ---------------- edge aggregation (R7 version: 4 feat x 64 agents) ----------
// agg[i,f] = sum_{j != i} rcp(1 + A_i U_j) * ln2 * log2(1 + B_i V_j)
// 4-way rcp batching with f32x2 packed FMA math.
__global__ __launch_bounds__(256) void k_edge(int sidx,
    const float* __restrict__ gamma, const float* __restrict__ beta)
{
    __shared__ __align__(16) float su[4][64];
    __shared__ __align__(16) float sv[4][64];
    __shared__ float wsum[8], wsq[8];
    __shared__ int   lastflag;

    const int tid  = threadIdx.x;
    const int i    = tid & 63;
    const int fl   = tid >> 6;
    const int f    = blockIdx.y * 4 + fl;
    const int node = blockIdx.x * NAG + i;
    const int eidx = f * NNODES + node;

    const float a  = g_E[0][eidx];
    const float u  = g_E[1][eidx];
    const float b  = g_E[2][eidx];
    const float vv = g_E[3][eidx];
    su[fl][i] = u;
    sv[fl][i] = vv;
    __syncthreads();

    const ulonglong2* pu = (const ulonglong2*)su[fl];
    const ulonglong2* pv = (const ulonglong2*)sv[fl];

    const unsigned long long ONE2 = pack2(1.f, 1.f);
    const unsigned long long a2   = pack2(a, a);
    const unsigned long long b2   = pack2(b, b);

    float acc = 0.f;
    #pragma unroll
    for (int jq = 0; jq < 16; jq++) {
        ulonglong2 Uq = pu[jq];     // (u0,u1),(u2,u3)
        ulonglong2 Vq = pv[jq];
        unsigned long long t1a = fma2(a2, Uq.x, ONE2);   // (t0,t1)
        unsigned long long t1b = fma2(a2, Uq.y, ONE2);   // (t2,t3)
        unsigned long long t2a = fma2(b2, Vq.x, ONE2);
        unsigned long long t2b = fma2(b2, Vq.y, ONE2);
        float x0, x1, x2, x3;
        unpack2(t2a, x0, x1);
        unpack2(t2b, x2, x3);
        float l0 = __log2f(x0), l1 = __log2f(x1);
        float l2 = __log2f(x2), l3 = __log2f(x3);
        unsigned long long tt = mul2(t1a, t1b);          // (t0t2, t1t3)
        float ttl, tth;
        unpack2(tt, ttl, tth);
        float D = ttl * tth;
        float r;
        asm("rcp.approx.f32 %0, %1;" : "=f"(r) : "f"(D));
        unsigned long long lp01 = pack2(l0, l1);
        unsigned long long lp23 = pack2(l2, l3);
        unsigned long long m = fma2(lp23, t1a, mul2(lp01, t1b));  // (m0,m1)
        float m0, m1;
        unpack2(m, m0, m1);
        float s = fmaf(ttl, m1, tth * m0);
        acc = fmaf(s, r, acc);
    }
    // subtract self term (j == i)
    {
        float t1 = fmaf(a, u, 1.f);
        float t2 = fmaf(b, vv, 1.f);
        float r;
        asm("rcp.approx.f32 %0, %1;" : "=f"(r) : "f"(t1));
        acc -= r * __log2f(t2);
    }
    const float aggv = acc * LN2F;
    g_agg[node * FDIM + f] = aggv;

    // BN stats partial sums
    float s = aggv, q = aggv * aggv;
    #pragma unroll
    for (int o = 16; o > 0; o >>= 1) {
        s += __shfl_down_sync(0xFFFFFFFFu, s, o);
        q += __shfl_down_sync(0xFFFFFFFFu, q, o);
    }
    if ((tid & 31) == 0) { wsum[tid >> 5] = s; wsq[tid >> 5] = q; }
    __syncthreads();
    if (tid < 4) {
        double S = (double)wsum[2 * tid] + (double)wsum[2 * tid + 1];
        double Q = (double)wsq[2 * tid]  + (double)wsq[2 * tid + 1];
        int ff = blockIdx.y * 4 + tid;
        atomicAdd(&g_sum[sidx][ff], S);
        atomicAdd(&g_sq[sidx][ff], Q);
        __threadfence();
    }
    __syncthreads();

    if (tid == 0) {
        int prev = atomicAdd(&g_cnt[sidx], 1);
        lastflag = (prev == NSAMP * (FDIM / 4) - 1);
    }
    __syncthreads();
    if (lastflag) {
        if (tid < FDIM) {
            double S = __ldcg(&g_sum[sidx][tid]);
            double Q = __ldcg(&g_sq[sidx][tid]);
            double mean = S * (1.0 / NNODES);
            double var  = Q * (1.0 / NNODES) - mean * mean;
            float inv = (float)(1.0 / sqrt(var + 1e-5));
            float g = gamma[tid];
            g_sc[sidx][tid] = inv * g;
            g_sh[sidx][tid] = beta[tid] - (float)mean * inv * g;
        }
    }
}

// ---------------- BatchNorm + residual + ReLU (final output) ----------------
__global__ __launch_bounds__(256) void k_bn(
    const float* __restrict__ xin,
    float* __restrict__ out, int sidx)
{
    const int t = threadIdx.x;
    const float* sc = g_sc[sidx];
    const float* sh = g_sh[sidx];

    #pragma unroll
    for (int rep = 0; rep < 2; rep++) {
        int q4 = blockIdx.x * 512 + rep * 256 + t;
        int base = q4 * 4;
        int f = base & 127;
        float4 ag = *(const float4*)(g_agg + base);
        float4 xi = *(const float4*)(xin + base);
        float4 scv = *(const float4*)(sc + f);
        float4 shv = *(const float4*)(sh + f);
        float4 o;
        o.x = fmaxf(fmaf(ag.x, scv.x, shv.x) + xi.x, 0.f);
        o.y = fmaxf(fmaf(ag.y, scv.y, shv.y) + xi.y, 0.f);
        o.z = fmaxf(fmaf(ag.z, scv.z, shv.z) + xi.z, 0.f);
        o.w = fmaxf(fmaf(ag.w, scv.w, shv.w) + xi.w, 0.f);
        *(float4*)(out + base) = o;
    }
}

// ---------------- launcher ---------------------------------------------------
extern "C" void kernel_launch(void* const* d_in, const int* in_sizes, int n_in,
                              void* d_out, int out_size)
{
    const float* gnn_in  = (const float*)d_in[0];
    const float* centers = (const float*)d_in[1];
    const float* Wf1 = (const float*)d_in[4];
    const float* bf1 = (const float*)d_in[5];
    const float* Ws1 = (const float*)d_in[6];
    const float* bs1 = (const float*)d_in[7];
    const float* g1  = (const float*)d_in[8];
    const float* be1 = (const float*)d_in[9];
    const float* Wf2 = (const float*)d_in[10];
    const float* bf2 = (const float*)d_in[11];
    const float* Ws2 = (const float*)d_in[12];
    const float* bs2 = (const float*)d_in[13];
    const float* g2  = (const float*)d_in[14];
    const float* be2 = (const float*)d_in[15];
    float* out = (float*)d_out;

    float* x1;   cudaGetSymbolAddress((void**)&x1, g_x1);
    float* aggp; cudaGetSymbolAddress((void**)&aggp, g_agg);

    static int smem_set = 0;
    if (!smem_set) {
        cudaFuncSetAttribute(k_gemm_tf32,
                             cudaFuncAttributeMaxDynamicSharedMemorySize,
                             GEMM_SMEM_BYTES);
        smem_set = 1;
    }

    dim3 gemm_grid(NNODES / 128, 4);      // 32 x 4 = 128 blocks, by == g
    dim3 edge_grid(NSAMP, FDIM / 4);      // 64 x 32 blocks
    int bn_blocks = (NNODES * FDIM) / (4 * 512);

    // ---- layer 1 ----
    k_gemm_tf32<<<gemm_grid, 256, GEMM_SMEM_BYTES>>>(
        gnn_in, gnn_in, x1, centers, Wf1, bf1, Ws1, bs1, 0, 0);
    k_edge<<<edge_grid, 256>>>(0, g1, be1);

    // ---- layer 2 (BN1 + residual + ReLU fused into the GEMM prologue) ----
    k_gemm_tf32<<<gemm_grid, 256, GEMM_SMEM_BYTES>>>(
        gnn_in, aggp, x1, centers, Wf2, bf2, Ws2, bs2, 1, 1);
    k_edge<<<edge_grid, 256>>>(1, g2, be2);
    k_bn<<<bn_blocks, 256>>>(x1, out, 1);
}